// round 14
// baseline (speedup 1.0000x reference)
#include <cuda_runtime.h>
#include <cstdint>
#include <cstddef>

#define BATCH 256
#define TSEQ  512
#define IDIM  64
#define HDIM  512
#define ODIM  512
#define GRID_STEP 128        // persistent CTAs (<=148 SMs, 1 CTA/SM, single wave)
#define STEP_THREADS 256     // 8 warps -> 2 per SMSP (latency hiding)

typedef unsigned long long ull;

// ---- scratch (static device allocations only) ----
__device__ float  g_xp[(size_t)TSEQ * BATCH * HDIM];   // [t][b][h], 256 MiB
// hidden state, transposed + splatted: g_ht[buf][h*BATCH + b] = {v, v}
__device__ float2 g_ht[2][(size_t)HDIM * BATCH];       // 2 MiB
__device__ unsigned g_bar;                             // grid barrier (self-resetting)

// ---- packed f32x2 helpers ----
__device__ __forceinline__ ull pk2(float lo, float hi) {
    ull r; asm("mov.b64 %0, {%1,%2};" : "=l"(r) : "f"(lo), "f"(hi)); return r;
}
__device__ __forceinline__ float2 upk2(ull v) {
    float2 r; asm("mov.b64 {%0,%1}, %2;" : "=f"(r.x), "=f"(r.y) : "l"(v)); return r;
}
__device__ __forceinline__ ull fma2(ull a, ull b, ull c) {
    ull d; asm("fma.rn.f32x2 %0, %1, %2, %3;" : "=l"(d) : "l"(a), "l"(b), "l"(c)); return d;
}

// ---- grid barrier (R3-identical: busy spin, single counter, self-reset) ----
__device__ __forceinline__ void bar_wait(unsigned target) {
    if (threadIdx.x == 0) {
        unsigned v;
        do {
            asm volatile("ld.acquire.gpu.global.u32 %0, [%1];"
                         : "=r"(v) : "l"(&g_bar) : "memory");
        } while (v < target);
    }
    __syncthreads();
}
__device__ __forceinline__ void bar_arrive(unsigned total) {
    __syncthreads();
    if (threadIdx.x == 0) {
        unsigned old;
        asm volatile("atom.release.gpu.global.add.u32 %0, [%1], %2;"
                     : "=r"(old) : "l"(&g_bar), "r"(1u) : "memory");
        if (old == total - 1u)
            asm volatile("st.relaxed.gpu.global.u32 [%0], %1;"
                         :: "l"(&g_bar), "r"(0u) : "memory");
    }
}

// pad kernel: preserves the launch pattern that put rnn at ncu's capture slot.
__global__ void pad_kernel() {}

// ============================================================================
// Kernel A: xp[t][b][:] = x[b][t][:] @ Whx + bh.  4 rows (same b) per CTA.
// ============================================================================
__global__ void __launch_bounds__(128) xproj_kernel(
    const float* __restrict__ x, const float* __restrict__ Whx,
    const float* __restrict__ bh)
{
    __shared__ float xs[4][IDIM];
    int row0 = blockIdx.x * 4;
    int b = row0 >> 9, t0 = row0 & (TSEQ - 1);
    int tid = threadIdx.x;
    for (int i = tid; i < 4 * IDIM; i += 128)
        xs[i >> 6][i & 63] = x[(size_t)(row0 + (i >> 6)) * IDIM + (i & 63)];
    __syncthreads();

    int j0 = tid * 4;
    ull a[4][2] = {};
    #pragma unroll 4
    for (int k = 0; k < IDIM; k++) {
        float4 w = *reinterpret_cast<const float4*>(Whx + (size_t)k * HDIM + j0);
        ull w01 = pk2(w.x, w.y), w23 = pk2(w.z, w.w);
        #pragma unroll
        for (int r = 0; r < 4; r++) {
            float xv = xs[r][k];
            ull x2 = pk2(xv, xv);
            a[r][0] = fma2(w01, x2, a[r][0]);
            a[r][1] = fma2(w23, x2, a[r][1]);
        }
    }
    float4 bv = *reinterpret_cast<const float4*>(bh + j0);
    #pragma unroll
    for (int r = 0; r < 4; r++) {
        float2 p0 = upk2(a[r][0]), p1 = upk2(a[r][1]);
        float4 o;
        o.x = p0.x + bv.x; o.y = p0.y + bv.y;
        o.z = p1.x + bv.z; o.w = p1.y + bv.w;
        *reinterpret_cast<float4*>(
            g_xp + ((size_t)(t0 + r) * BATCH + b) * HDIM + j0) = o;
    }
}

// ============================================================================
// Kernel B: persistent recurrence — R11 structure, 256 threads (8 warps).
// Grid (16 j, 8 b) = 128 CTAs; CTA tile 32j x 32b; thread tile 2j x 2b.
// Whh slice [512][32] SMEM (64 KB); h staged via double-buffered cp.async.cg
// in 4 chunks of [128 k][32 b] float2 (32 KB each buffer).
// Inner kl: LDS.64 W (j-pair) + LDS.128 h (2 splat-pairs) + 2 FFMA2.
// ============================================================================
__global__ void __launch_bounds__(STEP_THREADS, 1) rnn_persistent(
    const float* __restrict__ Whh)
{
    extern __shared__ char smraw[];
    float* ws = reinterpret_cast<float*>(smraw);          // [512][32]  64 KB
    char*  hsb = smraw + 65536;                           // 2 x 32 KB

    const int tid = threadIdx.x;
    const int jp = tid & 15;                // 16 j-pairs -> 32 j
    const int bp = tid >> 4;                // 16 b-pairs -> 32 b
    const int j0c = blockIdx.x * 32;
    const int b0c = blockIdx.y * 32;
    const int jl = jp * 2;                  // local j (pair base)
    const int bl = bp * 2;                  // local b (pair base, even)
    const int j0 = j0c + jl;
    const int b0 = b0c + bl;

    // ---- load Whh slice into SMEM (once) ----
    for (int i = tid; i < 512 * 8; i += STEP_THREADS) {
        int k = i >> 3, c = i & 7;
        *reinterpret_cast<float4*>(ws + k * 32 + c * 4) =
            *reinterpret_cast<const float4*>(Whh + (size_t)k * HDIM + j0c + c * 4);
    }
    __syncthreads();

    // staging map: chunk = [128 k][32 b] float2 (256B rows = 16 segs of 16B).
    // seg = tid&15, krow = tid>>4 (0..15); 8 passes stride 16.
    const int seg  = tid & 15;
    const int krow = tid >> 4;

    for (int t = 0; t < TSEQ; t++) {
        const float* xpt = g_xp + (size_t)t * BATCH * HDIM;
        float2 xv0 = *reinterpret_cast<const float2*>(xpt + (size_t)b0 * HDIM + j0);
        float2 xv1 = *reinterpret_cast<const float2*>(xpt + (size_t)(b0 + 1) * HDIM + j0);
        ull a0 = 0ull, a1 = 0ull;           // {j0,j1} @ b0, @ b1

        if (t > 0) {
            bar_wait((unsigned)t * GRID_STEP);
            const float2* hin = g_ht[(t - 1) & 1];

            // issue chunk 0 into buffer 0
            {
                const float2* src = hin + (size_t)krow * BATCH + b0c + seg * 2;
                uint32_t dst = (uint32_t)__cvta_generic_to_shared(
                    hsb + ((size_t)krow * 32 + seg * 2) * 8);
                #pragma unroll
                for (int p = 0; p < 8; p++)
                    asm volatile("cp.async.cg.shared.global [%0], [%1], 16;"
                                 :: "r"(dst + p * 4096), "l"(src + (size_t)p * 16 * BATCH)
                                 : "memory");
                asm volatile("cp.async.commit_group;" ::: "memory");
            }

            #pragma unroll
            for (int c = 0; c < 4; c++) {
                asm volatile("cp.async.wait_group 0;" ::: "memory");
                __syncthreads();
                if (c < 3) {
                    const float2* src = hin + (size_t)((c + 1) * 128 + krow) * BATCH
                                        + b0c + seg * 2;
                    uint32_t dst = (uint32_t)__cvta_generic_to_shared(
                        hsb + ((size_t)((c + 1) & 1)) * 32768
                            + ((size_t)krow * 32 + seg * 2) * 8);
                    #pragma unroll
                    for (int p = 0; p < 8; p++)
                        asm volatile("cp.async.cg.shared.global [%0], [%1], 16;"
                                     :: "r"(dst + p * 4096), "l"(src + (size_t)p * 16 * BATCH)
                                     : "memory");
                    asm volatile("cp.async.commit_group;" ::: "memory");
                }
                // compute chunk c from buffer c&1
                const float* wk = ws + (c * 128) * 32 + jl;
                const char*  hk = hsb + (c & 1) * 32768 + bl * 8;
                #pragma unroll 8
                for (int kl = 0; kl < 128; kl++) {
                    ull w2 = *reinterpret_cast<const ull*>(wk + (size_t)kl * 32);
                    ulonglong2 h2 = *reinterpret_cast<const ulonglong2*>(hk + (size_t)kl * 256);
                    a0 = fma2(w2, h2.x, a0);   // {j0,j1} @ b0
                    a1 = fma2(w2, h2.y, a1);   // {j0,j1} @ b1
                }
            }
        }

        // ---- epilogue: add xp, tanh, store splatted-transposed h ----
        float2* hout = g_ht[t & 1];
        float2 p0 = upk2(a0), p1 = upk2(a1);
        float o00 = tanhf(xv0.x + p0.x), o01 = tanhf(xv0.y + p0.y);  // b0: j0, j1
        float o10 = tanhf(xv1.x + p1.x), o11 = tanhf(xv1.y + p1.y);  // b1: j0, j1
        // fused float4 store per j row: {o_b0, o_b0, o_b1, o_b1}
        *reinterpret_cast<float4*>(&hout[(size_t)(j0 + 0) * BATCH + b0]) =
            make_float4(o00, o00, o10, o10);
        *reinterpret_cast<float4*>(&hout[(size_t)(j0 + 1) * BATCH + b0]) =
            make_float4(o01, o01, o11, o11);

        bar_arrive((unsigned)TSEQ * GRID_STEP);
    }
}

// ============================================================================
// Kernel C: out[b][:] = softmax(h_last @ Wph + bo). h_last = g_ht[1]
// (t=511 -> buffer 1), splatted-transposed: read .x at [k*BATCH + b].
// ============================================================================
__global__ void __launch_bounds__(128) out_softmax_kernel(
    const float* __restrict__ Wph, const float* __restrict__ bo,
    float* __restrict__ out)
{
    __shared__ float hsr[HDIM];
    __shared__ float red[128];
    int b = blockIdx.x, tid = threadIdx.x;
    for (int k = tid; k < HDIM; k += 128)
        hsr[k] = g_ht[1][(size_t)k * BATCH + b].x;
    __syncthreads();

    int j0 = tid * 4;
    ull a0 = 0ull, a1 = 0ull;
    #pragma unroll 8
    for (int k = 0; k < HDIM; k++) {
        float4 w = *reinterpret_cast<const float4*>(Wph + (size_t)k * ODIM + j0);
        ull hv = pk2(hsr[k], hsr[k]);
        a0 = fma2(pk2(w.x, w.y), hv, a0);
        a1 = fma2(pk2(w.z, w.w), hv, a1);
    }
    float4 bv = *reinterpret_cast<const float4*>(bo + j0);
    float2 p0 = upk2(a0), p1 = upk2(a1);
    float4 v;
    v.x = p0.x + bv.x; v.y = p0.y + bv.y;
    v.z = p1.x + bv.z; v.w = p1.y + bv.w;

    float m = fmaxf(fmaxf(v.x, v.y), fmaxf(v.z, v.w));
    red[tid] = m;
    __syncthreads();
    for (int s = 64; s > 0; s >>= 1) {
        if (tid < s) red[tid] = fmaxf(red[tid], red[tid + s]);
        __syncthreads();
    }
    m = red[0];
    __syncthreads();

    v.x = expf(v.x - m); v.y = expf(v.y - m);
    v.z = expf(v.z - m); v.w = expf(v.w - m);
    red[tid] = v.x + v.y + v.z + v.w;
    __syncthreads();
    for (int s = 64; s > 0; s >>= 1) {
        if (tid < s) red[tid] += red[tid + s];
        __syncthreads();
    }
    float inv = 1.0f / red[0];
    v.x *= inv; v.y *= inv; v.z *= inv; v.w *= inv;
    *reinterpret_cast<float4*>(out + (size_t)b * ODIM + j0) = v;
}

// ============================================================================
// Launch order matches R13's 5-launch pattern (rnn at index 3) so ncu's
// capture slot lands on rnn_persistent again.
// ============================================================================
extern "C" void kernel_launch(void* const* d_in, const int* in_sizes, int n_in,
                              void* d_out, int out_size)
{
    const float* x   = (const float*)d_in[0];
    const float* Whx = (const float*)d_in[1];
    const float* Whh = (const float*)d_in[2];
    const float* bh  = (const float*)d_in[3];
    const float* Wph = (const float*)d_in[4];
    const float* bo  = (const float*)d_in[5];
    float* out = (float*)d_out;

    cudaFuncSetAttribute(rnn_persistent,
                         cudaFuncAttributeMaxDynamicSharedMemorySize, 131072);

    pad_kernel<<<1, 32>>>();
    pad_kernel<<<1, 32>>>();
    xproj_kernel<<<BATCH * TSEQ / 4, 128>>>(x, Whx, bh);
    rnn_persistent<<<dim3(16, 8), STEP_THREADS, 131072>>>(Whh);
    out_softmax_kernel<<<BATCH, 128>>>(Wph, bo, out);
}

// round 15
// speedup vs baseline: 1.1482x; 1.1482x over previous
#include <cuda_runtime.h>
#include <cstdint>
#include <cstddef>

#define BATCH 256
#define TSEQ  512
#define IDIM  64
#define HDIM  512
#define ODIM  512
#define GRID_STEP 128        // persistent CTAs (<=148 SMs, 1 CTA/SM, single wave)
#define STEP_THREADS 256     // 8 warps: R11's 4-warp map x 2 k-halves

typedef unsigned long long ull;

// ---- scratch (static device allocations only) ----
__device__ float  g_xp[(size_t)TSEQ * BATCH * HDIM];   // [t][b][h], 256 MiB
// hidden state, transposed + splatted: g_ht[buf][h*BATCH + b] = {v, v}
__device__ float2 g_ht[2][(size_t)HDIM * BATCH];       // 2 MiB
__device__ unsigned g_bar;                             // grid barrier (self-resetting)

// ---- packed f32x2 helpers ----
__device__ __forceinline__ ull pk2(float lo, float hi) {
    ull r; asm("mov.b64 %0, {%1,%2};" : "=l"(r) : "f"(lo), "f"(hi)); return r;
}
__device__ __forceinline__ float2 upk2(ull v) {
    float2 r; asm("mov.b64 {%0,%1}, %2;" : "=f"(r.x), "=f"(r.y) : "l"(v)); return r;
}
__device__ __forceinline__ ull fma2(ull a, ull b, ull c) {
    ull d; asm("fma.rn.f32x2 %0, %1, %2, %3;" : "=l"(d) : "l"(a), "l"(b), "l"(c)); return d;
}
__device__ __forceinline__ ull add2(ull a, ull b) {
    ull d; asm("add.rn.f32x2 %0, %1, %2;" : "=l"(d) : "l"(a), "l"(b)); return d;
}

// fast tanh: 1 - 2/(e^{2x}+1), MUFU ex2 + rcp (rel err ~1e-6, vs thresh 1e-3)
__device__ __forceinline__ float tanh_fast(float x) {
    float e, r;
    asm("ex2.approx.f32 %0, %1;" : "=f"(e) : "f"(x * 2.885390082f)); // 2*log2(e)
    asm("rcp.approx.f32 %0, %1;" : "=f"(r) : "f"(e + 1.0f));
    return fmaf(-2.0f, r, 1.0f);
}

// ---- grid barrier (champion config: busy spin, single counter, self-reset) ----
__device__ __forceinline__ void bar_wait(unsigned target) {
    if (threadIdx.x == 0) {
        unsigned v;
        do {
            asm volatile("ld.acquire.gpu.global.u32 %0, [%1];"
                         : "=r"(v) : "l"(&g_bar) : "memory");
        } while (v < target);
    }
    __syncthreads();
}
__device__ __forceinline__ void bar_arrive(unsigned total) {
    __syncthreads();
    if (threadIdx.x == 0) {
        unsigned old;
        asm volatile("atom.release.gpu.global.add.u32 %0, [%1], %2;"
                     : "=r"(old) : "l"(&g_bar), "r"(1u) : "memory");
        if (old == total - 1u)
            asm volatile("st.relaxed.gpu.global.u32 [%0], %1;"
                         :: "l"(&g_bar), "r"(0u) : "memory");
    }
}

// pad kernel: preserves the launch pattern that put rnn at ncu's capture slot.
__global__ void pad_kernel() {}

// ============================================================================
// Kernel A: xp[t][b][:] = x[b][t][:] @ Whx + bh.  4 rows (same b) per CTA.
// ============================================================================
__global__ void __launch_bounds__(128) xproj_kernel(
    const float* __restrict__ x, const float* __restrict__ Whx,
    const float* __restrict__ bh)
{
    __shared__ float xs[4][IDIM];
    int row0 = blockIdx.x * 4;
    int b = row0 >> 9, t0 = row0 & (TSEQ - 1);
    int tid = threadIdx.x;
    for (int i = tid; i < 4 * IDIM; i += 128)
        xs[i >> 6][i & 63] = x[(size_t)(row0 + (i >> 6)) * IDIM + (i & 63)];
    __syncthreads();

    int j0 = tid * 4;
    ull a[4][2] = {};
    #pragma unroll 4
    for (int k = 0; k < IDIM; k++) {
        float4 w = *reinterpret_cast<const float4*>(Whx + (size_t)k * HDIM + j0);
        ull w01 = pk2(w.x, w.y), w23 = pk2(w.z, w.w);
        #pragma unroll
        for (int r = 0; r < 4; r++) {
            float xv = xs[r][k];
            ull x2 = pk2(xv, xv);
            a[r][0] = fma2(w01, x2, a[r][0]);
            a[r][1] = fma2(w23, x2, a[r][1]);
        }
    }
    float4 bv = *reinterpret_cast<const float4*>(bh + j0);
    #pragma unroll
    for (int r = 0; r < 4; r++) {
        float2 p0 = upk2(a[r][0]), p1 = upk2(a[r][1]);
        float4 o;
        o.x = p0.x + bv.x; o.y = p0.y + bv.y;
        o.z = p1.x + bv.z; o.w = p1.y + bv.w;
        *reinterpret_cast<float4*>(
            g_xp + ((size_t)(t0 + r) * BATCH + b) * HDIM + j0) = o;
    }
}

// ============================================================================
// Kernel B: persistent recurrence — R11 champion + warp k-split + fast tanh.
// Grid (16 j, 8 b) = 128 CTAs x 256 threads. CTA tile 32j x 32b.
// Warp w: wk = w&1 (k-half), wo = w>>1 (R11's warp id). Per-warp thread map
// IDENTICAL to R11 (jg=lane&7, bg=lane>>3, bl=wo*8+bg*2) -> same wavefront
// dedup per kl; each warp covers half the kls. Partials merged via smem.
// Inner kl: LDS.128 W + LDS.128 h-splats + 4 FFMA2 (zero packs).
// ============================================================================
__global__ void __launch_bounds__(STEP_THREADS, 1) rnn_persistent(
    const float* __restrict__ Whh)
{
    extern __shared__ char smraw[];
    float* ws  = reinterpret_cast<float*>(smraw);          // [512][32]  64 KB
    char*  hsb = smraw + 65536;                            // 2 x 32 KB
    ull*   redb = reinterpret_cast<ull*>(smraw + 131072);  // [128][4] ull, 4 KB

    const int tid  = threadIdx.x;
    const int lane = tid & 31;
    const int w    = tid >> 5;
    const int wk   = w & 1;                 // k-half
    const int wo   = w >> 1;                // R11 warp id 0..3
    const int jg = lane & 7, bg = lane >> 3;
    const int j0c = blockIdx.x * 32;
    const int b0c = blockIdx.y * 32;
    const int j0 = j0c + jg * 4;
    const int bl = wo * 8 + bg * 2;         // local b (even)
    const int b0 = b0c + bl;
    const int rid = wo * 32 + lane;         // 0..127 reduction slot

    // ---- load Whh slice into SMEM (once) ----
    for (int i = tid; i < 512 * 8; i += STEP_THREADS) {
        int k = i >> 3, c = i & 7;
        *reinterpret_cast<float4*>(ws + k * 32 + c * 4) =
            *reinterpret_cast<const float4*>(Whh + (size_t)k * HDIM + j0c + c * 4);
    }
    __syncthreads();

    // staging map (256 threads): chunk = [128 k][32 b] float2, 256B rows =
    // 16 segs of 16B. seg = tid&15, krow = tid>>4 (0..15), 8 passes stride 16.
    const int seg  = tid & 15;
    const int krow = tid >> 4;

    for (int t = 0; t < TSEQ; t++) {
        const float* xpt = g_xp + (size_t)t * BATCH * HDIM;
        float4 xv0, xv1;
        if (wk == 0) {   // epilogue owners prefetch xp
            xv0 = *reinterpret_cast<const float4*>(xpt + (size_t)b0 * HDIM + j0);
            xv1 = *reinterpret_cast<const float4*>(xpt + (size_t)(b0 + 1) * HDIM + j0);
        }
        ull a00 = 0ull, a10 = 0ull, a01 = 0ull, a11 = 0ull;

        if (t > 0) {
            bar_wait((unsigned)t * GRID_STEP);
            const float2* hin = g_ht[(t - 1) & 1];

            // issue chunk 0 into buffer 0
            {
                const float2* src = hin + (size_t)krow * BATCH + b0c + seg * 2;
                uint32_t dst = (uint32_t)__cvta_generic_to_shared(
                    hsb + ((size_t)krow * 32 + seg * 2) * 8);
                #pragma unroll
                for (int p = 0; p < 8; p++)
                    asm volatile("cp.async.cg.shared.global [%0], [%1], 16;"
                                 :: "r"(dst + p * 4096),
                                    "l"(src + (size_t)p * 16 * BATCH) : "memory");
                asm volatile("cp.async.commit_group;" ::: "memory");
            }

            #pragma unroll
            for (int c = 0; c < 4; c++) {
                asm volatile("cp.async.wait_group 0;" ::: "memory");
                __syncthreads();
                if (c < 3) {
                    const float2* src = hin + (size_t)((c + 1) * 128 + krow) * BATCH
                                        + b0c + seg * 2;
                    uint32_t dst = (uint32_t)__cvta_generic_to_shared(
                        hsb + ((size_t)((c + 1) & 1)) * 32768
                            + ((size_t)krow * 32 + seg * 2) * 8);
                    #pragma unroll
                    for (int p = 0; p < 8; p++)
                        asm volatile("cp.async.cg.shared.global [%0], [%1], 16;"
                                     :: "r"(dst + p * 4096),
                                        "l"(src + (size_t)p * 16 * BATCH) : "memory");
                    asm volatile("cp.async.commit_group;" ::: "memory");
                }
                // compute this warp's k-half of chunk c (buffer c&1)
                const float* wkp = ws + (c * 128 + wk * 64) * 32 + jg * 4;
                const char*  hk  = hsb + (c & 1) * 32768 + (size_t)wk * 64 * 256 + bl * 8;
                #pragma unroll 8
                for (int kl = 0; kl < 64; kl++) {
                    ulonglong2 w2 = *reinterpret_cast<const ulonglong2*>(wkp + (size_t)kl * 32);
                    ulonglong2 h2 = *reinterpret_cast<const ulonglong2*>(hk + (size_t)kl * 256);
                    a00 = fma2(w2.x, h2.x, a00);
                    a10 = fma2(w2.y, h2.x, a10);
                    a01 = fma2(w2.x, h2.y, a01);
                    a11 = fma2(w2.y, h2.y, a11);
                }
            }

            // merge k-halves: wk==1 publishes, wk==0 adds.
            if (wk == 1) {
                ull* d = redb + (size_t)rid * 4;
                d[0] = a00; d[1] = a10; d[2] = a01; d[3] = a11;
            }
            __syncthreads();
            if (wk == 0) {
                const ull* s = redb + (size_t)rid * 4;
                a00 = add2(a00, s[0]);
                a10 = add2(a10, s[1]);
                a01 = add2(a01, s[2]);
                a11 = add2(a11, s[3]);
            }
        }

        // ---- epilogue (wk==0 warps): add xp, fast tanh, splat-store h ----
        if (wk == 0) {
            float2* hout = g_ht[t & 1];
            float2 p0 = upk2(a00), p1 = upk2(a10), p2 = upk2(a01), p3 = upk2(a11);
            float o0[4] = { tanh_fast(xv0.x + p0.x), tanh_fast(xv0.y + p0.y),
                            tanh_fast(xv0.z + p1.x), tanh_fast(xv0.w + p1.y) };
            float o1[4] = { tanh_fast(xv1.x + p2.x), tanh_fast(xv1.y + p2.y),
                            tanh_fast(xv1.z + p3.x), tanh_fast(xv1.w + p3.y) };
            #pragma unroll
            for (int jj = 0; jj < 4; jj++) {
                hout[(size_t)(j0 + jj) * BATCH + b0]     = make_float2(o0[jj], o0[jj]);
                hout[(size_t)(j0 + jj) * BATCH + b0 + 1] = make_float2(o1[jj], o1[jj]);
            }
        }
        bar_arrive((unsigned)TSEQ * GRID_STEP);
    }
}

// ============================================================================
// Kernel C: out[b][:] = softmax(h_last @ Wph + bo). h_last = g_ht[1]
// (t=511 -> buffer 1), splatted-transposed: read .x at [k*BATCH + b].
// ============================================================================
__global__ void __launch_bounds__(128) out_softmax_kernel(
    const float* __restrict__ Wph, const float* __restrict__ bo,
    float* __restrict__ out)
{
    __shared__ float hsr[HDIM];
    __shared__ float red[128];
    int b = blockIdx.x, tid = threadIdx.x;
    for (int k = tid; k < HDIM; k += 128)
        hsr[k] = g_ht[1][(size_t)k * BATCH + b].x;
    __syncthreads();

    int j0 = tid * 4;
    ull a0 = 0ull, a1 = 0ull;
    #pragma unroll 8
    for (int k = 0; k < HDIM; k++) {
        float4 w = *reinterpret_cast<const float4*>(Wph + (size_t)k * ODIM + j0);
        ull hv = pk2(hsr[k], hsr[k]);
        a0 = fma2(pk2(w.x, w.y), hv, a0);
        a1 = fma2(pk2(w.z, w.w), hv, a1);
    }
    float4 bv = *reinterpret_cast<const float4*>(bo + j0);
    float2 p0 = upk2(a0), p1 = upk2(a1);
    float4 v;
    v.x = p0.x + bv.x; v.y = p0.y + bv.y;
    v.z = p1.x + bv.z; v.w = p1.y + bv.w;

    float m = fmaxf(fmaxf(v.x, v.y), fmaxf(v.z, v.w));
    red[tid] = m;
    __syncthreads();
    for (int s = 64; s > 0; s >>= 1) {
        if (tid < s) red[tid] = fmaxf(red[tid], red[tid + s]);
        __syncthreads();
    }
    m = red[0];
    __syncthreads();

    v.x = expf(v.x - m); v.y = expf(v.y - m);
    v.z = expf(v.z - m); v.w = expf(v.w - m);
    red[tid] = v.x + v.y + v.z + v.w;
    __syncthreads();
    for (int s = 64; s > 0; s >>= 1) {
        if (tid < s) red[tid] += red[tid + s];
        __syncthreads();
    }
    float inv = 1.0f / red[0];
    v.x *= inv; v.y *= inv; v.z *= inv; v.w *= inv;
    *reinterpret_cast<float4*>(out + (size_t)b * ODIM + j0) = v;
}

// ============================================================================
extern "C" void kernel_launch(void* const* d_in, const int* in_sizes, int n_in,
                              void* d_out, int out_size)
{
    const float* x   = (const float*)d_in[0];
    const float* Whx = (const float*)d_in[1];
    const float* Whh = (const float*)d_in[2];
    const float* bh  = (const float*)d_in[3];
    const float* Wph = (const float*)d_in[4];
    const float* bo  = (const float*)d_in[5];
    float* out = (float*)d_out;

    cudaFuncSetAttribute(rnn_persistent,
                         cudaFuncAttributeMaxDynamicSharedMemorySize, 135168);

    pad_kernel<<<1, 32>>>();
    pad_kernel<<<1, 32>>>();
    xproj_kernel<<<BATCH * TSEQ / 4, 128>>>(x, Whx, bh);
    rnn_persistent<<<dim3(16, 8), STEP_THREADS, 135168>>>(Whh);
    out_softmax_kernel<<<BATCH, 128>>>(Wph, bo, out);
}

// round 16
// speedup vs baseline: 1.3852x; 1.2064x over previous
#include <cuda_runtime.h>
#include <cstdint>
#include <cstddef>

#define BATCH 256
#define TSEQ  512
#define IDIM  64
#define HDIM  512
#define ODIM  512
#define GRID_STEP 128        // persistent CTAs (<=148 SMs, 1 CTA/SM, single wave)
#define STEP_THREADS 256     // 8 warps: 4-warp map x 2 k-halves

typedef unsigned long long ull;

// ---- scratch (static device allocations only) ----
__device__ float  g_xp[(size_t)TSEQ * BATCH * HDIM];   // [t][b][h], 256 MiB
// hidden state, k-paired transposed: g_ht4[buf][jp*128 + bp] =
//   {h[2jp][2bp], h[2jp][2bp+1], h[2jp+1][2bp], h[2jp+1][2bp+1]}
__device__ float4 g_ht4[2][(size_t)(HDIM / 2) * (BATCH / 2)];  // 1 MiB
__device__ unsigned g_bar;                             // grid barrier (self-resetting)

// ---- packed f32x2 helpers ----
__device__ __forceinline__ ull pk2(float lo, float hi) {
    ull r; asm("mov.b64 %0, {%1,%2};" : "=l"(r) : "f"(lo), "f"(hi)); return r;
}
__device__ __forceinline__ float2 upk2(ull v) {
    float2 r; asm("mov.b64 {%0,%1}, %2;" : "=f"(r.x), "=f"(r.y) : "l"(v)); return r;
}
__device__ __forceinline__ ull fma2(ull a, ull b, ull c) {
    ull d; asm("fma.rn.f32x2 %0, %1, %2, %3;" : "=l"(d) : "l"(a), "l"(b), "l"(c)); return d;
}
__device__ __forceinline__ ull add2(ull a, ull b) {
    ull d; asm("add.rn.f32x2 %0, %1, %2;" : "=l"(d) : "l"(a), "l"(b)); return d;
}

// fast tanh: 1 - 2/(e^{2x}+1)  (MUFU ex2+rcp, rel err ~1e-6 vs 1e-3 thresh)
__device__ __forceinline__ float tanh_fast(float x) {
    float e, r;
    asm("ex2.approx.f32 %0, %1;" : "=f"(e) : "f"(x * 2.885390082f));
    asm("rcp.approx.f32 %0, %1;" : "=f"(r) : "f"(e + 1.0f));
    return fmaf(-2.0f, r, 1.0f);
}

// ---- grid barrier (champion: busy spin, single counter, self-reset) ----
__device__ __forceinline__ void bar_wait(unsigned target) {
    if (threadIdx.x == 0) {
        unsigned v;
        do {
            asm volatile("ld.acquire.gpu.global.u32 %0, [%1];"
                         : "=r"(v) : "l"(&g_bar) : "memory");
        } while (v < target);
    }
    __syncthreads();
}
__device__ __forceinline__ void bar_arrive(unsigned total) {
    __syncthreads();
    if (threadIdx.x == 0) {
        unsigned old;
        asm volatile("atom.release.gpu.global.add.u32 %0, [%1], %2;"
                     : "=r"(old) : "l"(&g_bar), "r"(1u) : "memory");
        if (old == total - 1u)
            asm volatile("st.relaxed.gpu.global.u32 [%0], %1;"
                         :: "l"(&g_bar), "r"(0u) : "memory");
    }
}

__global__ void pad_kernel() {}

// ============================================================================
// Kernel A: xp[t][b][:] = x[b][t][:] @ Whx + bh.  8 rows (same b) per CTA.
// ============================================================================
__global__ void __launch_bounds__(128) xproj_kernel(
    const float* __restrict__ x, const float* __restrict__ Whx,
    const float* __restrict__ bh)
{
    __shared__ float xs[8][IDIM];
    int row0 = blockIdx.x * 8;
    int b = row0 >> 9, t0 = row0 & (TSEQ - 1);
    int tid = threadIdx.x;
    for (int i = tid; i < 8 * IDIM; i += 128)
        xs[i >> 6][i & 63] = x[(size_t)(row0 + (i >> 6)) * IDIM + (i & 63)];
    __syncthreads();

    int j0 = tid * 4;
    ull a[8][2] = {};
    #pragma unroll 4
    for (int k = 0; k < IDIM; k++) {
        float4 w = *reinterpret_cast<const float4*>(Whx + (size_t)k * HDIM + j0);
        ull w01 = pk2(w.x, w.y), w23 = pk2(w.z, w.w);
        #pragma unroll
        for (int r = 0; r < 8; r++) {
            float xv = xs[r][k];
            ull x2 = pk2(xv, xv);
            a[r][0] = fma2(w01, x2, a[r][0]);
            a[r][1] = fma2(w23, x2, a[r][1]);
        }
    }
    float4 bv = *reinterpret_cast<const float4*>(bh + j0);
    #pragma unroll
    for (int r = 0; r < 8; r++) {
        float2 p0 = upk2(a[r][0]), p1 = upk2(a[r][1]);
        float4 o;
        o.x = p0.x + bv.x; o.y = p0.y + bv.y;
        o.z = p1.x + bv.z; o.w = p1.y + bv.w;
        *reinterpret_cast<float4*>(
            g_xp + ((size_t)(t0 + r) * BATCH + b) * HDIM + j0) = o;
    }
}

// ============================================================================
// Kernel B: persistent recurrence — R15 skeleton, k-paired h layout.
// Grid (16 j, 8 b) = 128 CTAs x 256 threads; CTA tile 32j x 32b.
// Warp w: wk = w&1 (k-half), wo = w>>1; lane: jg=lane&7, bg=lane>>3;
// thread tile 4j x 2b. Whh [512][32] smem (64 KB). h staged per 128-k chunk
// as [64 kp][16 bp] float4 (16 KB, double buffered).
// Inner 2-kl: 2x LDS.128 W + 1x LDS.128 h(k-pair,b-pair) + 4 pk2 + 8 FFMA2
// -> 3 smem wavefronts per warp per 2 kl (vs 4 in R15).
// ============================================================================
__global__ void __launch_bounds__(STEP_THREADS, 1) rnn_persistent(
    const float* __restrict__ Whh)
{
    extern __shared__ char smraw[];
    float* ws   = reinterpret_cast<float*>(smraw);          // [512][32]  64 KB
    char*  hsb  = smraw + 65536;                            // 2 x 16 KB
    ull*   redb = reinterpret_cast<ull*>(smraw + 65536 + 32768);  // [128][4], 4 KB

    const int tid  = threadIdx.x;
    const int lane = tid & 31;
    const int w    = tid >> 5;
    const int wk   = w & 1;                 // k-half
    const int wo   = w >> 1;                // 0..3
    const int jg = lane & 7, bg = lane >> 3;
    const int j0c = blockIdx.x * 32;
    const int b0c = blockIdx.y * 32;
    const int j0 = j0c + jg * 4;
    const int bl = wo * 8 + bg * 2;         // local b (even)
    const int b0 = b0c + bl;
    const int bpl = bl >> 1;                // local b-pair index (0..15)
    const int rid = wo * 32 + lane;         // 0..127 reduction slot

    // ---- load Whh slice [512][32] into SMEM (once) ----
    for (int i = tid; i < 512 * 8; i += STEP_THREADS) {
        int k = i >> 3, c = i & 7;
        *reinterpret_cast<float4*>(ws + k * 32 + c * 4) =
            *reinterpret_cast<const float4*>(Whh + (size_t)k * HDIM + j0c + c * 4);
    }
    __syncthreads();

    // staging map: chunk = [64 kp][16 bp] float4 (256B rows, 16 segs of 16B).
    // seg = tid&15 (one bp each), row = tid>>4 (0..15), 4 passes stride 16.
    const int seg  = tid & 15;
    const int srow = tid >> 4;
    const int bp0c = b0c >> 1;              // global bp base for this CTA

    for (int t = 0; t < TSEQ; t++) {
        const float* xpt = g_xp + (size_t)t * BATCH * HDIM;
        float4 xv0, xv1;
        if (wk == 0) {
            xv0 = *reinterpret_cast<const float4*>(xpt + (size_t)b0 * HDIM + j0);
            xv1 = *reinterpret_cast<const float4*>(xpt + (size_t)(b0 + 1) * HDIM + j0);
        }
        ull a00 = 0ull, a10 = 0ull, a01 = 0ull, a11 = 0ull;

        if (t > 0) {
            bar_wait((unsigned)t * GRID_STEP);
            const float4* hin = g_ht4[(t - 1) & 1];

            auto issue = [&](int c) {
                // global rows kp = c*64 + (srow + p*16); 16B per (row, seg)
                #pragma unroll
                for (int p = 0; p < 4; p++) {
                    int kp = c * 64 + srow + p * 16;
                    const float4* src = hin + (size_t)kp * 128 + bp0c + seg;
                    uint32_t dst = (uint32_t)__cvta_generic_to_shared(
                        hsb + (size_t)(c & 1) * 16384
                            + ((size_t)(srow + p * 16) * 16 + seg) * 16);
                    asm volatile("cp.async.cg.shared.global [%0], [%1], 16;"
                                 :: "r"(dst), "l"(src) : "memory");
                }
                asm volatile("cp.async.commit_group;" ::: "memory");
            };
            auto compute = [&](int c) {
                // this warp's k-half: kls [wk*64, wk*64+64) -> kprs 0..31
                const float* wkp = ws + (size_t)(c * 128 + wk * 64) * 32 + jg * 4;
                const char*  hk  = hsb + (size_t)(c & 1) * 16384
                                   + (size_t)wk * 32 * 256 + bpl * 16;
                #pragma unroll 8
                for (int kpr = 0; kpr < 32; kpr++) {
                    ulonglong2 wA = *reinterpret_cast<const ulonglong2*>(
                        wkp + (size_t)kpr * 64);          // k even
                    ulonglong2 wB = *reinterpret_cast<const ulonglong2*>(
                        wkp + (size_t)kpr * 64 + 32);     // k odd
                    float4 h4 = *reinterpret_cast<const float4*>(
                        hk + (size_t)kpr * 256);          // {k0b0,k0b1,k1b0,k1b1}
                    ull s00 = pk2(h4.x, h4.x), s01 = pk2(h4.y, h4.y);
                    ull s10 = pk2(h4.z, h4.z), s11 = pk2(h4.w, h4.w);
                    a00 = fma2(wA.x, s00, a00);
                    a10 = fma2(wA.y, s00, a10);
                    a01 = fma2(wA.x, s01, a01);
                    a11 = fma2(wA.y, s01, a11);
                    a00 = fma2(wB.x, s10, a00);
                    a10 = fma2(wB.y, s10, a10);
                    a01 = fma2(wB.x, s11, a01);
                    a11 = fma2(wB.y, s11, a11);
                }
            };

            issue(0);
            asm volatile("cp.async.wait_group 0;" ::: "memory");
            __syncthreads();
            issue(1);
            compute(0);
            asm volatile("cp.async.wait_group 0;" ::: "memory");
            __syncthreads();
            issue(2);
            compute(1);
            asm volatile("cp.async.wait_group 0;" ::: "memory");
            __syncthreads();
            issue(3);
            compute(2);
            asm volatile("cp.async.wait_group 0;" ::: "memory");
            __syncthreads();
            compute(3);

            // merge k-halves: wk==1 publishes, wk==0 adds.
            if (wk == 1) {
                ull* d = redb + (size_t)rid * 4;
                d[0] = a00; d[1] = a10; d[2] = a01; d[3] = a11;
            }
            __syncthreads();
            if (wk == 0) {
                const ull* s = redb + (size_t)rid * 4;
                a00 = add2(a00, s[0]);
                a10 = add2(a10, s[1]);
                a01 = add2(a01, s[2]);
                a11 = add2(a11, s[3]);
            }
        }

        // ---- epilogue (wk==0): add xp, fast tanh, k-paired float4 stores ----
        if (wk == 0) {
            float4* hout = g_ht4[t & 1];
            float2 p0 = upk2(a00), p1 = upk2(a10), p2 = upk2(a01), p3 = upk2(a11);
            float o0[4] = { tanh_fast(xv0.x + p0.x), tanh_fast(xv0.y + p0.y),
                            tanh_fast(xv0.z + p1.x), tanh_fast(xv0.w + p1.y) };
            float o1[4] = { tanh_fast(xv1.x + p2.x), tanh_fast(xv1.y + p2.y),
                            tanh_fast(xv1.z + p3.x), tanh_fast(xv1.w + p3.y) };
            int jp0 = j0 >> 1;          // j0 = 4-aligned -> j-pairs jp0, jp0+1
            int bp  = b0 >> 1;
            hout[(size_t)jp0 * 128 + bp]       = make_float4(o0[0], o1[0], o0[1], o1[1]);
            hout[(size_t)(jp0 + 1) * 128 + bp] = make_float4(o0[2], o1[2], o0[3], o1[3]);
        }
        bar_arrive((unsigned)TSEQ * GRID_STEP);
    }
}

// ============================================================================
// Kernel C: out[b][:] = softmax(h_last @ Wph + bo). h_last = g_ht4[1]
// (t=511 -> buffer 1), k-paired layout: (k,b) at [k>>1][b>>1][(k&1)*2+(b&1)].
// ============================================================================
__global__ void __launch_bounds__(128) out_softmax_kernel(
    const float* __restrict__ Wph, const float* __restrict__ bo,
    float* __restrict__ out)
{
    __shared__ float hsr[HDIM];
    __shared__ float red[128];
    int b = blockIdx.x, tid = threadIdx.x;
    const float* hl = reinterpret_cast<const float*>(g_ht4[1]);
    for (int k = tid; k < HDIM; k += 128)
        hsr[k] = hl[((size_t)(k >> 1) * 128 + (b >> 1)) * 4 + (k & 1) * 2 + (b & 1)];
    __syncthreads();

    int j0 = tid * 4;
    ull a0 = 0ull, a1 = 0ull;
    #pragma unroll 8
    for (int k = 0; k < HDIM; k++) {
        float4 wv = *reinterpret_cast<const float4*>(Wph + (size_t)k * ODIM + j0);
        ull hv = pk2(hsr[k], hsr[k]);
        a0 = fma2(pk2(wv.x, wv.y), hv, a0);
        a1 = fma2(pk2(wv.z, wv.w), hv, a1);
    }
    float4 bv = *reinterpret_cast<const float4*>(bo + j0);
    float2 p0 = upk2(a0), p1 = upk2(a1);
    float4 v;
    v.x = p0.x + bv.x; v.y = p0.y + bv.y;
    v.z = p1.x + bv.z; v.w = p1.y + bv.w;

    float m = fmaxf(fmaxf(v.x, v.y), fmaxf(v.z, v.w));
    red[tid] = m;
    __syncthreads();
    for (int s = 64; s > 0; s >>= 1) {
        if (tid < s) red[tid] = fmaxf(red[tid], red[tid + s]);
        __syncthreads();
    }
    m = red[0];
    __syncthreads();

    v.x = expf(v.x - m); v.y = expf(v.y - m);
    v.z = expf(v.z - m); v.w = expf(v.w - m);
    red[tid] = v.x + v.y + v.z + v.w;
    __syncthreads();
    for (int s = 64; s > 0; s >>= 1) {
        if (tid < s) red[tid] += red[tid + s];
        __syncthreads();
    }
    float inv = 1.0f / red[0];
    v.x *= inv; v.y *= inv; v.z *= inv; v.w *= inv;
    *reinterpret_cast<float4*>(out + (size_t)b * ODIM + j0) = v;
}

// ============================================================================
extern "C" void kernel_launch(void* const* d_in, const int* in_sizes, int n_in,
                              void* d_out, int out_size)
{
    const float* x   = (const float*)d_in[0];
    const float* Whx = (const float*)d_in[1];
    const float* Whh = (const float*)d_in[2];
    const float* bh  = (const float*)d_in[3];
    const float* Wph = (const float*)d_in[4];
    const float* bo  = (const float*)d_in[5];
    float* out = (float*)d_out;

    cudaFuncSetAttribute(rnn_persistent,
                         cudaFuncAttributeMaxDynamicSharedMemorySize, 102400);

    pad_kernel<<<1, 32>>>();
    pad_kernel<<<1, 32>>>();
    xproj_kernel<<<BATCH * TSEQ / 8, 128>>>(x, Whx, bh);
    rnn_persistent<<<dim3(16, 8), STEP_THREADS, 102400>>>(Whh);
    out_softmax_kernel<<<BATCH, 128>>>(Wph, bo, out);
}